// round 8
// baseline (speedup 1.0000x reference)
#include <cuda_runtime.h>
#include <cuda_fp16.h>
#include <mma.h>
#include <cstdint>

#define NN 100000
#define NE 3200000
#define DEG_SCALE 33554432.0f   // 2^25 fixed-point for packed degree

using namespace nvcuda;

// ---------------- scratch (device globals; no allocation allowed) ----------
__device__ __align__(16) unsigned long long g_pack[NN]; // {cnt<<40 | deg*2^25}
__device__ __align__(16) float g_dinv[NN];
__device__ __align__(16) int   g_cnt[NN];
__device__ __align__(16) int   g_off[NN];
__device__ __align__(16) int   g_cur[NN];
__device__ __align__(16) int   g_bsum[512];
__device__ int g_is64;

__device__ __align__(16) uint2 g_edge[NE];      // CSR payload: {src, norm bits}

__device__ __align__(16) __half g_t1h[NN * 32]; // x @ W1
__device__ __align__(16) __half g_h1h[NN * 32]; // elu layer-1 out
__device__ __align__(16) __half g_s2h[NN * 32]; // A @ h1
__device__ __align__(16) __half g_h2h[NN * 64]; // elu layer-2 out
__device__ __align__(16) __half g_s3h[NN * 64]; // A @ h2

// ---------------- dtype detect: int64 vs int32 edge_index -----------------
__global__ void k_detect(const int* __restrict__ ei32) {
    __shared__ int cnt;
    if (threadIdx.x == 0) cnt = 0;
    __syncthreads();
    int zeros = 0;
    for (int i = threadIdx.x; i < 1024; i += blockDim.x)
        if (ei32[2 * i + 1] == 0) zeros++;
    atomicAdd(&cnt, zeros);
    __syncthreads();
    if (threadIdx.x == 0) g_is64 = (cnt > 900) ? 1 : 0;
}

__device__ __forceinline__ void load_edge(const int* __restrict__ ei32,
                                          int e, int E, int n, int& r, int& c) {
    if (g_is64) {
        r = ei32[2 * (long long)e];
        c = ei32[2 * ((long long)E + e)];
    } else {
        r = ei32[e];
        c = ei32[E + e];
    }
    if ((unsigned)r >= (unsigned)n) r = 0;
    if ((unsigned)c >= (unsigned)n) c = 0;
}

// ---------------- prep ------------------------------------------------------
__global__ void k_init(int n) {
    int i = blockIdx.x * blockDim.x + threadIdx.x;
    if (i < n) g_pack[i] = (unsigned long long)DEG_SCALE;  // deg=1 (self), cnt=0
}

__global__ void k_prep(const int* __restrict__ ei32,
                       const float* __restrict__ ea, int E, int n) {
    int e = blockIdx.x * blockDim.x + threadIdx.x;
    if (e >= E) return;
    int c;
    if (g_is64) c = ei32[2 * ((long long)E + e)];
    else        c = ei32[E + e];
    if ((unsigned)c >= (unsigned)n) c = 0;
    const unsigned long long add =
        (1ULL << 40) | (unsigned long long)(fmaxf(ea[e], 0.f) * DEG_SCALE + 0.5f);
    atomicAdd(&g_pack[c], add);
}

__global__ void k_dinv(int n) {
    int i = blockIdx.x * blockDim.x + threadIdx.x;
    if (i >= n) return;
    const unsigned long long p = g_pack[i];
    g_cnt[i] = (int)(p >> 40);
    const float d = (float)(p & 0xFFFFFFFFFFULL) * (1.0f / DEG_SCALE);
    g_dinv[i] = (d > 0.0f) ? rsqrtf(fmaxf(d, 1e-30f)) : 0.0f;
}

// ---------------- 3-kernel exclusive scan of g_cnt -> g_off ----------------
__global__ void k_scan1(int n) {
    __shared__ int sh[256];
    const int t = threadIdx.x;
    const int i = blockIdx.x * 256 + t;
    int v = (i < n) ? g_cnt[i] : 0;
    sh[t] = v;
    __syncthreads();
    for (int d = 1; d < 256; d <<= 1) {
        int u = (t >= d) ? sh[t - d] : 0;
        __syncthreads();
        sh[t] += u;
        __syncthreads();
    }
    if (i < n) g_off[i] = sh[t] - v;
    if (t == 255) g_bsum[blockIdx.x] = sh[255];
}

__global__ void k_scan2(int nb) {
    __shared__ int sh[512];
    const int t = threadIdx.x;
    int v = (t < nb) ? g_bsum[t] : 0;
    sh[t] = v;
    __syncthreads();
    for (int d = 1; d < 512; d <<= 1) {
        int u = (t >= d) ? sh[t - d] : 0;
        __syncthreads();
        sh[t] += u;
        __syncthreads();
    }
    if (t < nb) g_bsum[t] = sh[t] - v;
}

__global__ void k_scan3(int n) {
    int i = blockIdx.x * 256 + threadIdx.x;
    if (i < n) g_off[i] += g_bsum[blockIdx.x];
}

// ---------------- CSR fill --------------------------------------------------
__global__ void k_fill(const int* __restrict__ ei32,
                       const float* __restrict__ ea, int E, int n) {
    int e = blockIdx.x * blockDim.x + threadIdx.x;
    if (e >= E) return;
    int r, c;
    load_edge(ei32, e, E, n, r, c);
    const int pos = atomicAdd(&g_cur[c], 1);
    const float w = g_dinv[r] * ea[e] * g_dinv[c];
    g_edge[pos] = make_uint2((unsigned)r, __float_as_uint(w));
}

// ---------------- WMMA GEMM: Y[n,FOUT] = X[n,FIN] @ W[FIN,FOUT] (+b, elu) ---
// 256 threads = 8 warps arranged WR x WC. Block node tile = WR*16.
// A staged fp16 in smem (converted from fp32 or copied fp16); W fp16 in smem.
// fp32 accumulate; epilogue via smem with fused bias/ELU; out fp32 or fp16.
template <int FIN, int FOUT, int WR, int WC, bool BIAS, bool ELU, bool OUTF,
          typename IT>
__global__ void k_wmma(const IT* __restrict__ X, const float* __restrict__ W,
                       const float* __restrict__ b, float* __restrict__ Yf,
                       __half* __restrict__ Yh, int n) {
    constexpr int MB  = WR * 16;       // nodes per block
    constexpr int LDA = FIN + 8;       // padded smem lda (multiple of 8)
    constexpr int CPW = FOUT / WC;     // columns per warp
    constexpr int CF  = CPW / 16;      // col fragments per warp
    constexpr bool INF = (sizeof(IT) == 4);

    __shared__ __align__(32) __half Ah[MB * LDA];
    __shared__ __align__(32) __half Wh[FIN * FOUT];
    __shared__ __align__(32) float  Cs[MB * FOUT];

    const int tid = threadIdx.x;
    const int wid = tid / 32;
    const int wr = wid / WC;
    const int wc = wid % WC;
    const int node0 = blockIdx.x * MB;

    // stage W (fp32 -> fp16)
    for (int i = tid; i < FIN * FOUT; i += 256)
        Wh[i] = __float2half(W[i]);

    // stage A
    if (INF) {
        const float* Xf = (const float*)X;
        for (int i = tid; i < MB * FIN; i += 256) {
            const int ln = i / FIN, k = i % FIN;
            const int node = node0 + ln;
            Ah[ln * LDA + k] =
                (node < n) ? __float2half(Xf[(size_t)node * FIN + k])
                           : __float2half(0.f);
        }
    } else {
        const __half2* Xh = (const __half2*)X;
        for (int i = tid; i < MB * (FIN / 2); i += 256) {
            const int ln = i / (FIN / 2), k2 = i % (FIN / 2);
            const int node = node0 + ln;
            __half2 v = (node < n) ? Xh[(size_t)node * (FIN / 2) + k2]
                                   : __floats2half2_rn(0.f, 0.f);
            *(__half2*)&Ah[ln * LDA + 2 * k2] = v;
        }
    }
    __syncthreads();

    wmma::fragment<wmma::matrix_a, 16, 16, 16, __half, wmma::row_major> fa;
    wmma::fragment<wmma::matrix_b, 16, 16, 16, __half, wmma::row_major> fb;
    wmma::fragment<wmma::accumulator, 16, 16, 16, float> fc[CF];
#pragma unroll
    for (int cf = 0; cf < CF; cf++) wmma::fill_fragment(fc[cf], 0.0f);

#pragma unroll
    for (int k0 = 0; k0 < FIN; k0 += 16) {
        wmma::load_matrix_sync(fa, Ah + wr * 16 * LDA + k0, LDA);
#pragma unroll
        for (int cf = 0; cf < CF; cf++) {
            wmma::load_matrix_sync(fb, Wh + k0 * FOUT + wc * CPW + cf * 16, FOUT);
            wmma::mma_sync(fc[cf], fa, fb, fc[cf]);
        }
    }

#pragma unroll
    for (int cf = 0; cf < CF; cf++)
        wmma::store_matrix_sync(Cs + wr * 16 * FOUT + wc * CPW + cf * 16,
                                fc[cf], FOUT, wmma::mem_row_major);
    __syncthreads();

    // epilogue
    for (int i = tid; i < MB * FOUT; i += 256) {
        const int ln = i / FOUT, f = i % FOUT;
        const int node = node0 + ln;
        if (node >= n) continue;
        float v = Cs[i];
        if (BIAS) v += b[f];
        if (ELU)  v = (v > 0.f) ? v : expm1f(v);
        if (OUTF) Yf[(size_t)node * FOUT + f] = v;
        else      Yh[(size_t)node * FOUT + f] = __float2half(v);
    }
}

// ---------------- fused CSR aggregate ---------------------------------------
// out[i] = sum_{e in seg(i)} gh[src(e)]*norm(e) + gh[i]*dinv[i]^2 (+b, elu)
// F/8 lanes per node; each lane owns 8 halfs (one 16B load per edge). fp16 out.
template <int F, bool BE>
__global__ void k_agg(const __half* __restrict__ gh, const float* __restrict__ b,
                      __half* __restrict__ outh, int n) {
    constexpr int LPE = F / 8;
    const long long tid = (long long)blockIdx.x * blockDim.x + threadIdx.x;
    const int node = (int)(tid / LPE);
    const int s = (int)(tid % LPE);
    if (node >= n) return;

    const int base = g_off[node];
    const int deg  = g_cnt[node];

    float a0 = 0.f, a1 = 0.f, a2 = 0.f, a3 = 0.f;
    float a4 = 0.f, a5 = 0.f, a6 = 0.f, a7 = 0.f;
    int k = 0;
#define GATH(ED)                                                               \
    {                                                                          \
        const float w_ = __uint_as_float((ED).y);                              \
        const uint4 raw_ = *(const uint4*)(gh + (size_t)(ED).x * F + s * 8);   \
        const float2 p0_ = __half22float2(*(const __half2*)&raw_.x);           \
        const float2 p1_ = __half22float2(*(const __half2*)&raw_.y);           \
        const float2 p2_ = __half22float2(*(const __half2*)&raw_.z);           \
        const float2 p3_ = __half22float2(*(const __half2*)&raw_.w);           \
        a0 += p0_.x * w_; a1 += p0_.y * w_;                                    \
        a2 += p1_.x * w_; a3 += p1_.y * w_;                                    \
        a4 += p2_.x * w_; a5 += p2_.y * w_;                                    \
        a6 += p3_.x * w_; a7 += p3_.y * w_;                                    \
    }
    for (; k + 4 <= deg; k += 4) {
        const uint2 e0 = g_edge[base + k],     e1 = g_edge[base + k + 1];
        const uint2 e2 = g_edge[base + k + 2], e3 = g_edge[base + k + 3];
        GATH(e0) GATH(e1) GATH(e2) GATH(e3)
    }
    for (; k < deg; k++) {
        const uint2 e0 = g_edge[base + k];
        GATH(e0)
    }
#undef GATH

    // self-loop
    float dv = g_dinv[node]; dv *= dv;
    {
        const uint4 raw = *(const uint4*)(gh + (size_t)node * F + s * 8);
        const float2 p0 = __half22float2(*(const __half2*)&raw.x);
        const float2 p1 = __half22float2(*(const __half2*)&raw.y);
        const float2 p2 = __half22float2(*(const __half2*)&raw.z);
        const float2 p3 = __half22float2(*(const __half2*)&raw.w);
        a0 += p0.x * dv; a1 += p0.y * dv;
        a2 += p1.x * dv; a3 += p1.y * dv;
        a4 += p2.x * dv; a5 += p2.y * dv;
        a6 += p3.x * dv; a7 += p3.y * dv;
    }
    if (BE) {
        a0 += b[s * 8 + 0]; a1 += b[s * 8 + 1];
        a2 += b[s * 8 + 2]; a3 += b[s * 8 + 3];
        a4 += b[s * 8 + 4]; a5 += b[s * 8 + 5];
        a6 += b[s * 8 + 6]; a7 += b[s * 8 + 7];
        a0 = (a0 > 0.f) ? a0 : expm1f(a0);
        a1 = (a1 > 0.f) ? a1 : expm1f(a1);
        a2 = (a2 > 0.f) ? a2 : expm1f(a2);
        a3 = (a3 > 0.f) ? a3 : expm1f(a3);
        a4 = (a4 > 0.f) ? a4 : expm1f(a4);
        a5 = (a5 > 0.f) ? a5 : expm1f(a5);
        a6 = (a6 > 0.f) ? a6 : expm1f(a6);
        a7 = (a7 > 0.f) ? a7 : expm1f(a7);
    }
    __half2* hp = (__half2*)(outh + (size_t)node * F + s * 8);
    hp[0] = __floats2half2_rn(a0, a1);
    hp[1] = __floats2half2_rn(a2, a3);
    hp[2] = __floats2half2_rn(a4, a5);
    hp[3] = __floats2half2_rn(a6, a7);
}

// ---------------- launch ---------------------------------------------------
static inline int cdiv(long long a, int b) { return (int)((a + b - 1) / b); }

extern "C" void kernel_launch(void* const* d_in, const int* in_sizes, int n_in,
                              void* d_out, int out_size) {
    const float* x  = (const float*)d_in[0];
    const int*   ei = (const int*)d_in[1];
    const float* ea = (const float*)d_in[2];
    const float* W1 = (const float*)d_in[3];
    const float* b1 = (const float*)d_in[4];
    const float* W2 = (const float*)d_in[5];
    const float* b2 = (const float*)d_in[6];
    const float* W3 = (const float*)d_in[7];
    const float* b3 = (const float*)d_in[8];
    float* out = (float*)d_out;

    const int n = in_sizes[0] / 128;   // 100000
    const int E = in_sizes[2];         // 3200000

    void *p_off, *p_cur, *p_t1h, *p_h1h, *p_s2h, *p_h2h, *p_s3h;
    cudaGetSymbolAddress(&p_off, g_off);
    cudaGetSymbolAddress(&p_cur, g_cur);
    cudaGetSymbolAddress(&p_t1h, g_t1h);
    cudaGetSymbolAddress(&p_h1h, g_h1h);
    cudaGetSymbolAddress(&p_s2h, g_s2h);
    cudaGetSymbolAddress(&p_h2h, g_h2h);
    cudaGetSymbolAddress(&p_s3h, g_s3h);

    const int T = 256;
    const int nb = cdiv(n, 256);

    // --- prep: degrees, dinv, CSR build ---
    k_detect<<<1, 256>>>(ei);
    k_init<<<cdiv(n, T), T>>>(n);
    k_prep<<<cdiv(E, T), T>>>(ei, ea, E, n);
    k_dinv<<<cdiv(n, T), T>>>(n);
    k_scan1<<<nb, 256>>>(n);
    k_scan2<<<1, 512>>>(nb);
    k_scan3<<<nb, 256>>>(n);
    cudaMemcpyAsync(p_cur, p_off, (size_t)n * sizeof(int),
                    cudaMemcpyDeviceToDevice);
    k_fill<<<cdiv(E, T), T>>>(ei, ea, E, n);

    // --- layer 1: t1 = x@W1 ; h1 = elu(A t1 + b1) ---
    k_wmma<128, 32, 4, 2, false, false, false, float><<<cdiv(n, 64), 256>>>(
        x, W1, nullptr, nullptr, (__half*)p_t1h, n);
    k_agg<32, true><<<cdiv((long long)n * 4, T), T>>>(
        (const __half*)p_t1h, b1, (__half*)p_h1h, n);

    // --- layer 2: s2 = A h1 ; h2 = elu(s2@W2 + b2) ---
    k_agg<32, false><<<cdiv((long long)n * 4, T), T>>>(
        (const __half*)p_h1h, nullptr, (__half*)p_s2h, n);
    k_wmma<32, 64, 2, 4, true, true, false, __half><<<cdiv(n, 32), 256>>>(
        (const __half*)p_s2h, W2, b2, nullptr, (__half*)p_h2h, n);

    // --- layer 3: s3 = A h2 ; out = s3@W3 + b3 ---
    k_agg<64, false><<<cdiv((long long)n * 8, T), T>>>(
        (const __half*)p_h2h, nullptr, (__half*)p_s3h, n);
    k_wmma<64, 128, 2, 4, true, false, true, __half><<<cdiv(n, 32), 256>>>(
        (const __half*)p_s3h, W3, b3, out, nullptr, n);
}